// round 16
// baseline (speedup 1.0000x reference)
#include <cuda_runtime.h>
#include <cuda_bf16.h>
#include <cstdint>

#define NN 20000
#define NE 640000
#define P_PATH 512
#define S_SUB 64
#define DHID 256
#define PAD 128  // padded-CSR stride; max degree for this dataset ~57 << 128

typedef unsigned long long ull;

// ---------------- scratch (static device globals; no allocation) ----------------
static __device__ __align__(16) float g_agg[NN * 128];
static __device__ __align__(16) float g_part[NN * 256];
static __device__ __align__(16) float g_h1[NN * 24];
static __device__ __align__(16) float g_h2[NN * 64];
static __device__ __align__(16) float g_h3[NN * 128];
static __device__ __align__(16) float g_h4[NN * 256];
static __device__ __align__(16) float g_w3t[64 * 128];   // W3^T [K=64][N=128]
static __device__ __align__(16) float g_w4t[128 * 256];  // W4^T [K=128][N=256]
static __device__ int g_cnt[NN];
static __device__ int g_srcs[NN * PAD];
static __device__ int g_ticket2;
static __device__ float g_c[3 * 1024];
static __device__ __align__(16) float g_r0[3 * P_PATH * 256];
static __device__ __align__(16) float g_gates[3 * P_PATH * 1024];
static __device__ float g_xg[P_PATH];

__device__ __forceinline__ float sigm(float x) { return 1.f / (1.f + __expf(-x)); }

__device__ __forceinline__ void ffma2(ull& acc, ull a, ull b) {
    asm("fma.rn.f32x2 %0, %1, %2, %0;" : "+l"(acc) : "l"(a), "l"(b));
}
__device__ __forceinline__ float hsum2(ull v) {
    return __uint_as_float((unsigned)v) + __uint_as_float((unsigned)(v >> 32));
}

// ---------------- init: zero cnt + xg, transpose W3/W4 (one kernel) ----------------
__global__ void init_kernel(const float* __restrict__ W3, float* __restrict__ w3t,
                            const float* __restrict__ W4, float* __restrict__ w4t,
                            int* __restrict__ cnt, float* __restrict__ xg) {
    int i = blockIdx.x * 256 + threadIdx.x;
    if (i < NN) cnt[i] = 0;
    if (i < P_PATH) xg[i] = 0.f;
    if (i < 64 * 128) {
        int n = i % 128, k = i / 128;
        w3t[k * 128 + n] = W3[n * 64 + k];
    }
    if (i < 128 * 256) {
        int n = i % 256, k = i / 256;
        w4t[k * 256 + n] = W4[n * 128 + k];
    }
}

// ---------------- padded-CSR bucket: srcs[d*PAD + pos] = s ----------------
__global__ void bucket_kernel(const int* __restrict__ src, const int* __restrict__ dst,
                              int* __restrict__ cnt, int* __restrict__ srcs, int E) {
    int base = (blockIdx.x * blockDim.x + threadIdx.x) * 4;
    if (base + 3 < E) {
        int4 s4 = *reinterpret_cast<const int4*>(src + base);
        int4 d4 = *reinterpret_cast<const int4*>(dst + base);
        int p0 = atomicAdd(&cnt[d4.x], 1);
        int p1 = atomicAdd(&cnt[d4.y], 1);
        int p2 = atomicAdd(&cnt[d4.z], 1);
        int p3 = atomicAdd(&cnt[d4.w], 1);
        if (p0 < PAD) srcs[d4.x * PAD + p0] = s4.x;
        if (p1 < PAD) srcs[d4.y * PAD + p1] = s4.y;
        if (p2 < PAD) srcs[d4.z * PAD + p2] = s4.z;
        if (p3 < PAD) srcs[d4.w * PAD + p3] = s4.w;
    } else {
        for (int e = base; e < E; e++) {
            int p = atomicAdd(&cnt[dst[e]], 1);
            if (p < PAD) srcs[dst[e] * PAD + p] = src[e];
        }
    }
}

// ---------------- direct gather aggregation (large D) ----------------
template <int D>
__global__ void aggregate_k(const float* __restrict__ h, const int* __restrict__ cnt,
                            const int* __restrict__ srcs, float* __restrict__ outp) {
    constexpr int C = D / 4;
    int idx = blockIdx.x * blockDim.x + threadIdx.x;
    if (idx >= NN * C) return;
    int node = idx / C;
    int c = idx - node * C;
    const float4* hp = reinterpret_cast<const float4*>(h);
    float4 acc = hp[(size_t)node * C + c];
    int len = cnt[node];
    const int* sp = srcs + (size_t)node * PAD;
#pragma unroll 8
    for (int j = 0; j < len; j++) {
        int s = __ldg(&sp[j]);
        float4 v = hp[(size_t)s * C + c];
        acc.x += v.x;
        acc.y += v.y;
        acc.z += v.z;
        acc.w += v.w;
    }
    reinterpret_cast<float4*>(outp)[idx] = acc;
}

// ---------------- sliced aggregation (small D) ----------------
template <int D, int NS>
__global__ void aggregate_sliced(const float* __restrict__ h, const int* __restrict__ cnt,
                                 const int* __restrict__ srcs, float* __restrict__ part) {
    constexpr int C = D / 4;
    int idx = blockIdx.x * blockDim.x + threadIdx.x;
    if (idx >= NN * C * NS) return;
    int slice = idx / (NN * C);
    int rem = idx - slice * NN * C;
    int node = rem / C;
    int c = rem - node * C;
    const float4* hp = reinterpret_cast<const float4*>(h);
    int len = cnt[node];
    int a = (len * slice) / NS;
    int b = (len * (slice + 1)) / NS;
    const int* sp = srcs + (size_t)node * PAD;
    float4 acc = {0.f, 0.f, 0.f, 0.f};
#pragma unroll 4
    for (int j = a; j < b; j++) {
        int s = __ldg(&sp[j]);
        float4 v = hp[(size_t)s * C + c];
        acc.x += v.x;
        acc.y += v.y;
        acc.z += v.z;
        acc.w += v.w;
    }
    reinterpret_cast<float4*>(part)[idx] = acc;
}

// ---------------- small GIN GEMM (layers 1-2): out = relu((xin + sum part) @ W^T + b) ------
template <int K, int N, int NP, int T, int RPB, int NSLICE>
__global__ void gemm_relu(const float* __restrict__ xin, const float* __restrict__ part,
                          const float* __restrict__ W, const float* __restrict__ b,
                          float* __restrict__ out, int nrows) {
    constexpr int LDK = K + 4;
    constexpr int G = T / NP;
    constexpr int RPT = RPB / G;
    extern __shared__ float sm[];
    float* sW = sm;
    float* sR = sm + N * LDK;
    int tid = threadIdx.x;
    for (int i = tid; i < K * N; i += T) {
        int j = i / K, k = i - j * K;
        sW[j * LDK + k] = W[i];
    }
    int row0 = blockIdx.x * RPB;
    for (int i = tid; i < RPB * K; i += T) {
        int r = i / K, k = i - r * K;
        int row = row0 + r;
        float v = 0.f;
        if (row < nrows) {
            v = xin[(size_t)row * K + k];
#pragma unroll
            for (int s = 0; s < NSLICE; s++) v += part[((size_t)s * NN + row) * K + k];
        }
        sR[i] = v;
    }
    __syncthreads();
    int j = tid % NP;
    int rg = tid / NP;
    if (j < N) {
        float acc[RPT];
#pragma unroll
        for (int t = 0; t < RPT; t++) acc[t] = 0.f;
        for (int k = 0; k < K; k += 4) {
            float4 w4 = *reinterpret_cast<const float4*>(&sW[j * LDK + k]);
#pragma unroll
            for (int t = 0; t < RPT; t++) {
                float4 s4 = *reinterpret_cast<const float4*>(&sR[(rg + t * G) * K + k]);
                acc[t] += s4.x * w4.x + s4.y * w4.y + s4.z * w4.z + s4.w * w4.w;
            }
        }
        float bj = b[j];
#pragma unroll
        for (int t = 0; t < RPT; t++) {
            int row = row0 + rg + t * G;
            if (row < nrows) out[(size_t)row * N + j] = fmaxf(acc[t] + bj, 0.f);
        }
    }
}

// ---------------- register-tiled GEMM (layers 3-4), k-paired f32x2 ----------------
template <int K, int N>
__global__ void gemm_rt(const float* __restrict__ X, const float* __restrict__ WT,
                        const float* __restrict__ b, float* __restrict__ out, int nrows) {
    constexpr int TM = 64, TN = 64;
    constexpr int RSF = K + 2;
    extern __shared__ float sm[];
    float* sA = sm;            // [TM][K]
    float* sBt = sm + TM * K;  // [TN][RSF]
    int tid = threadIdx.x;
    int row0 = blockIdx.x * TM, n0 = blockIdx.y * TN;

    float4* sA4 = reinterpret_cast<float4*>(sA);
    for (int i = tid; i < TM * (K / 4); i += 256) {
        int kq = i % (K / 4), m = i / (K / 4);
        int row = row0 + m;
        float4 v = {0.f, 0.f, 0.f, 0.f};
        if (row < nrows) v = *reinterpret_cast<const float4*>(&X[(size_t)row * K + 4 * kq]);
        sA4[m * (K / 4) + kq] = v;
    }
    for (int i = tid; i < K * (TN / 4); i += 256) {
        int nq = i % (TN / 4), k = i / (TN / 4);
        float4 v = *reinterpret_cast<const float4*>(&WT[(size_t)k * N + n0 + 4 * nq]);
        sBt[(4 * nq + 0) * RSF + k] = v.x;
        sBt[(4 * nq + 1) * RSF + k] = v.y;
        sBt[(4 * nq + 2) * RSF + k] = v.z;
        sBt[(4 * nq + 3) * RSF + k] = v.w;
    }
    __syncthreads();

    int tx = tid % 16, ty = tid / 16;
    ull c2[4][4];
#pragma unroll
    for (int i = 0; i < 4; i++)
#pragma unroll
        for (int j = 0; j < 4; j++) c2[i][j] = 0ull;

#pragma unroll 8
    for (int kp = 0; kp < K / 2; kp++) {
        ull av[4], bv[4];
#pragma unroll
        for (int i = 0; i < 4; i++)
            av[i] = *reinterpret_cast<const ull*>(&sA[(ty * 4 + i) * K + 2 * kp]);
#pragma unroll
        for (int jj = 0; jj < 4; jj++)
            bv[jj] = *reinterpret_cast<const ull*>(&sBt[(tx + 16 * jj) * RSF + 2 * kp]);
#pragma unroll
        for (int i = 0; i < 4; i++)
#pragma unroll
            for (int jj = 0; jj < 4; jj++) ffma2(c2[i][jj], av[i], bv[jj]);
    }

#pragma unroll
    for (int i = 0; i < 4; i++) {
        int row = row0 + ty * 4 + i;
        if (row < nrows) {
#pragma unroll
            for (int jj = 0; jj < 4; jj++) {
                int n = n0 + tx + 16 * jj;
                out[(size_t)row * N + n] = fmaxf(hsum2(c2[i][jj]) + b[n], 0.f);
            }
        }
    }
}

// ---------------- attention (R9 form: grid (P[+4], 3); fused cvec/LSTM/xg/final) -----------
template <int PASS>
__global__ void attn_kernel(const float* __restrict__ h4, const int* __restrict__ pn,
                            const float* __restrict__ gates, const float* __restrict__ bih,
                            const float* __restrict__ bhh, const float* __restrict__ Wg,
                            const float* __restrict__ Wih, const float* __restrict__ Whh,
                            float* __restrict__ cvec, float* __restrict__ r0out,
                            float* __restrict__ xg, int* __restrict__ ticket2,
                            const float* __restrict__ bg, const float* __restrict__ Wl1,
                            const float* __restrict__ bl1, const float* __restrict__ Wl2,
                            const float* __restrict__ bl2, const float* __restrict__ Wl3,
                            const float* __restrict__ bl3, float* __restrict__ out) {
    int p = blockIdx.x, k = blockIdx.y;
    extern __shared__ float smdyn[];
    float* sx = smdyn;
    float* sq = smdyn + 64 * 256;
    float* dots = sq + 256;
    int* spn = (int*)(dots + 64);
    int tid = threadIdx.x;

    if (PASS == 0 && p >= P_PATH) {  // cvec worker blocks
        int j = (p - P_PATH) * 256 + tid;
        {
            const float* bi = bih + k * 1024;
            const float* bh = bhh + k * 1024;
            float gi = bi[tid] + bh[tid];
            float gg = bi[512 + tid] + bh[512 + tid];
            float go = bi[768 + tid] + bh[768 + tid];
            float cs = sigm(gi) * tanhf(gg);
            sq[tid] = sigm(go) * tanhf(cs);
        }
        __syncthreads();
        const float* wi = Wih + ((size_t)k * 1024 + j) * 512;
        const float* wh = Whh + ((size_t)k * 1024 + j) * 256;
        float acc = bih[k * 1024 + j] + bhh[k * 1024 + j];
        for (int d = 0; d < 256; d += 4) {
            float4 a = *reinterpret_cast<const float4*>(wi + d);
            float4 bq = *reinterpret_cast<const float4*>(wh + d);
            float4 s = *reinterpret_cast<const float4*>(&sq[d]);
            acc += (a.x + bq.x) * s.x + (a.y + bq.y) * s.y + (a.z + bq.z) * s.z +
                   (a.w + bq.w) * s.w;
        }
        cvec[k * 1024 + j] = acc;
        return;
    }

    {
        const float* bi = bih + k * 1024;
        const float* bh = bhh + k * 1024;
        float bgi = bi[tid] + bh[tid];
        float bgg = bi[512 + tid] + bh[512 + tid];
        float bgo = bi[768 + tid] + bh[768 + tid];
        float cs0 = sigm(bgi) * tanhf(bgg);
        if (PASS == 0) {
            sq[tid] = sigm(bgo) * tanhf(cs0);
        } else {
            const float* g = gates + ((size_t)(k * P_PATH + p)) * 1024;
            float gi = g[tid], gf = g[256 + tid], gg = g[512 + tid], go = g[768 + tid];
            float cs = sigm(gf) * cs0 + sigm(gi) * tanhf(gg);
            sq[tid] = sigm(go) * tanhf(cs);
        }
    }
    if (tid < 64) spn[tid] = pn[p * 64 + tid];
    __syncthreads();

    const float4* h4v = reinterpret_cast<const float4*>(h4);
    float4* sxv = reinterpret_cast<float4*>(sx);
    for (int i = tid; i < 64 * 64; i += 256) {
        int s = i >> 6, c = i & 63;
        sxv[i] = h4v[(size_t)spn[s] * 64 + c];
    }
    __syncthreads();

    int w = tid >> 5, lane = tid & 31;
    for (int s = w; s < 64; s += 8) {
        const float* xr = sx + s * 256;
        float part = 0.f;
#pragma unroll
        for (int m = 0; m < 8; m++) part += xr[lane + 32 * m] * sq[lane + 32 * m];
        for (int off = 16; off; off >>= 1) part += __shfl_down_sync(0xffffffffu, part, off);
        if (lane == 0) dots[s] = part;
    }
    __syncthreads();
    if (w == 0) {
        float a = dots[lane], b = dots[lane + 32];
        float mx = fmaxf(a, b);
        for (int off = 16; off; off >>= 1) mx = fmaxf(mx, __shfl_xor_sync(0xffffffffu, mx, off));
        float e0 = __expf(a - mx), e1 = __expf(b - mx);
        float sum = e0 + e1;
        for (int off = 16; off; off >>= 1) sum += __shfl_xor_sync(0xffffffffu, sum, off);
        float inv = 1.f / sum;
        dots[lane] = e0 * inv;
        dots[lane + 32] = e1 * inv;
    }
    __syncthreads();
    float acc = 0.f;
#pragma unroll 8
    for (int s = 0; s < 64; s++) acc += dots[s] * sx[s * 256 + tid];

    if (PASS == 0) {
        r0out[((size_t)k * P_PATH + p) * 256 + tid] = acc;
        return;
    }

    float part = sq[tid] * Wg[k * 512 + tid] + acc * Wg[k * 512 + 256 + tid];
    __syncthreads();
    for (int off = 16; off; off >>= 1) part += __shfl_xor_sync(0xffffffffu, part, off);
    if (lane == 0) dots[w] = part;
    __syncthreads();
    __shared__ int s_last;
    if (tid == 0) {
        float t = 0.f;
#pragma unroll
        for (int i = 0; i < 8; i++) t += dots[i];
        atomicAdd(&xg[p], t);
        __threadfence();
        int tk = atomicAdd(ticket2, 1);
        s_last = (tk == 3 * P_PATH - 1);
    }
    __syncthreads();
    if (!s_last) return;

    // ---- final MLP (last-arriving block) ----
    __threadfence();
    float* sxg = sx;
    float* sz1 = sx + 512;
    float* sz2 = sx + 512 + 256;
    float bgv = bg[0];
    sxg[tid] = xg[tid] + bgv;
    sxg[tid + 256] = xg[tid + 256] + bgv;
    __syncthreads();
    {
        float a = bl1[tid];
        const float* wv = Wl1 + (size_t)tid * 512;
        for (int q = 0; q < 512; q += 4) {
            float4 w4 = *reinterpret_cast<const float4*>(wv + q);
            float4 x4 = *reinterpret_cast<const float4*>(&sxg[q]);
            a += w4.x * x4.x + w4.y * x4.y + w4.z * x4.z + w4.w * x4.w;
        }
        sz1[tid] = tanhf(a);
    }
    __syncthreads();
    if (tid < 64) {
        float bacc = bl2[tid];
        const float* w2 = Wl2 + (size_t)tid * 256;
        for (int hh = 0; hh < 256; hh += 4) {
            float4 w4 = *reinterpret_cast<const float4*>(w2 + hh);
            float4 z4 = *reinterpret_cast<const float4*>(&sz1[hh]);
            bacc += w4.x * z4.x + w4.y * z4.y + w4.z * z4.z + w4.w * z4.w;
        }
        sz2[tid] = fmaxf(bacc, 0.f);
    }
    __syncthreads();
    if (tid == 0) {
        float cacc = bl3[0];
        for (int j = 0; j < 64; j++) cacc += sz2[j] * Wl3[j];
        out[0] = 1.f / (1.f + __expf(-cacc));
        *ticket2 = 0;  // reset for next graph replay
    }
}

// ---------------- gates1 = c[k,:] + r0 @ Wih[:, D:2D]^T  (f32x2, 32-row tiles) -----------
__global__ void gates_gemm(const float* __restrict__ r0, const float* __restrict__ Wih,
                           const float* __restrict__ c, float* __restrict__ gates) {
    constexpr int RT = 32;
    int ct = blockIdx.x, rt = blockIdx.y, k = blockIdx.z;
    __shared__ __align__(16) float sR[RT * 256];
    int tid = threadIdx.x;
    const float* rbase = r0 + ((size_t)k * P_PATH + rt * RT) * 256;
    for (int i = tid; i < RT * 256; i += 256) sR[i] = rbase[i];
    __syncthreads();
    int j = ct * 256 + tid;
    const ull* wrow = reinterpret_cast<const ull*>(Wih + ((size_t)k * 1024 + j) * 512 + 256);
    ull acc2[RT];
#pragma unroll
    for (int r = 0; r < RT; r++) acc2[r] = 0ull;
    for (int d = 0; d < 256; d += 4) {
        ull w01 = wrow[d / 2];
        ull w23 = wrow[d / 2 + 1];
#pragma unroll
        for (int r = 0; r < RT; r++) {
            const ull* sp = reinterpret_cast<const ull*>(&sR[r * 256]);
            ffma2(acc2[r], w01, sp[d / 2]);
            ffma2(acc2[r], w23, sp[d / 2 + 1]);
        }
    }
    float cj = c[k * 1024 + j];
#pragma unroll
    for (int r = 0; r < RT; r++)
        gates[((size_t)k * P_PATH + rt * RT + r) * 1024 + j] = hsum2(acc2[r]) + cj;
}

// ---------------- host launcher ----------------
extern "C" void kernel_launch(void* const* d_in, const int* in_sizes, int n_in,
                              void* d_out, int out_size) {
    const float* h = (const float*)d_in[0];
    const int* src = (const int*)d_in[1];
    const int* dst = (const int*)d_in[2];
    const int* pn = (const int*)d_in[3];
    const float* W1 = (const float*)d_in[4];
    const float* b1 = (const float*)d_in[5];
    const float* W2 = (const float*)d_in[6];
    const float* b2 = (const float*)d_in[7];
    const float* W3 = (const float*)d_in[8];
    const float* b3 = (const float*)d_in[9];
    const float* W4 = (const float*)d_in[10];
    const float* b4 = (const float*)d_in[11];
    const float* Wih = (const float*)d_in[12];
    const float* Whh = (const float*)d_in[13];
    const float* bih = (const float*)d_in[14];
    const float* bhh = (const float*)d_in[15];
    const float* Wg = (const float*)d_in[16];
    const float* bg = (const float*)d_in[17];
    const float* Wl1 = (const float*)d_in[18];
    const float* bl1 = (const float*)d_in[19];
    const float* Wl2 = (const float*)d_in[20];
    const float* bl2 = (const float*)d_in[21];
    const float* Wl3 = (const float*)d_in[22];
    const float* bl3 = (const float*)d_in[23];
    int E = in_sizes[1];
    float* out = (float*)d_out;

    float *agg, *part, *h1, *h2, *h3, *h4, *w3t, *w4t, *cvec, *r0, *gates, *xg;
    int *cnt, *srcs, *ticket2;
    cudaGetSymbolAddress((void**)&agg, g_agg);
    cudaGetSymbolAddress((void**)&part, g_part);
    cudaGetSymbolAddress((void**)&h1, g_h1);
    cudaGetSymbolAddress((void**)&h2, g_h2);
    cudaGetSymbolAddress((void**)&h3, g_h3);
    cudaGetSymbolAddress((void**)&h4, g_h4);
    cudaGetSymbolAddress((void**)&w3t, g_w3t);
    cudaGetSymbolAddress((void**)&w4t, g_w4t);
    cudaGetSymbolAddress((void**)&cvec, g_c);
    cudaGetSymbolAddress((void**)&r0, g_r0);
    cudaGetSymbolAddress((void**)&gates, g_gates);
    cudaGetSymbolAddress((void**)&xg, g_xg);
    cudaGetSymbolAddress((void**)&cnt, g_cnt);
    cudaGetSymbolAddress((void**)&srcs, g_srcs);
    cudaGetSymbolAddress((void**)&ticket2, g_ticket2);

    const int smem1 = (24 * 12 + 32 * 8) * 4;
    const int smem2 = (64 * 28 + 32 * 24) * 4;
    const int rt3_smem = (64 * 64 + 64 * 66) * 4;    // ~33.3 KB
    const int rt4_smem = (64 * 128 + 64 * 130) * 4;  // ~66.0 KB
    cudaFuncSetAttribute(gemm_rt<64, 128>, cudaFuncAttributeMaxDynamicSharedMemorySize,
                         rt3_smem);
    cudaFuncSetAttribute(gemm_rt<128, 256>, cudaFuncAttributeMaxDynamicSharedMemorySize,
                         rt4_smem);
    const int attn_smem = (64 * 256 + 256 + 64 + 64) * 4;
    cudaFuncSetAttribute(attn_kernel<0>, cudaFuncAttributeMaxDynamicSharedMemorySize, attn_smem);
    cudaFuncSetAttribute(attn_kernel<1>, cudaFuncAttributeMaxDynamicSharedMemorySize, attn_smem);

    // ---- init + padded-CSR bucket (2 nodes replace 5) ----
    init_kernel<<<(128 * 256 + 255) / 256, 256>>>(W3, w3t, W4, w4t, cnt, xg);
    bucket_kernel<<<(E / 4 + 255) / 256, 256>>>(src, dst, cnt, srcs, E);

    // ---- 4 GIN layers ----
    aggregate_sliced<8, 8><<<(NN * 2 * 8 + 255) / 256, 256>>>(h, cnt, srcs, part);
    gemm_relu<8, 24, 32, 256, 32, 8><<<(NN + 31) / 32, 256, smem1>>>(h, part, W1, b1, h1, NN);

    aggregate_sliced<24, 4><<<(NN * 6 * 4 + 255) / 256, 256>>>(h1, cnt, srcs, part);
    gemm_relu<24, 64, 64, 256, 32, 4><<<(NN + 31) / 32, 256, smem2>>>(h1, part, W2, b2, h2, NN);

    aggregate_k<64><<<(NN * 16 + 255) / 256, 256>>>(h2, cnt, srcs, agg);
    gemm_rt<64, 128><<<dim3((NN + 63) / 64, 2), 256, rt3_smem>>>(agg, w3t, b3, h3, NN);

    aggregate_k<128><<<(NN * 32 + 255) / 256, 256>>>(h3, cnt, srcs, agg);
    gemm_rt<128, 256><<<dim3((NN + 63) / 64, 4), 256, rt4_smem>>>(agg, w4t, b4, h4, NN);

    // ---- Set2Set (R9 form) ----
    attn_kernel<0><<<dim3(P_PATH + 4, 3), 256, attn_smem>>>(
        h4, pn, nullptr, bih, bhh, Wg, Wih, Whh, cvec, r0, xg, ticket2, bg, Wl1, bl1, Wl2, bl2,
        Wl3, bl3, out);
    gates_gemm<<<dim3(4, P_PATH / 32, 3), 256>>>(r0, Wih, cvec, gates);
    attn_kernel<1><<<dim3(P_PATH, 3), 256, attn_smem>>>(
        h4, pn, gates, bih, bhh, Wg, Wih, Whh, cvec, r0, xg, ticket2, bg, Wl1, bl1, Wl2, bl2,
        Wl3, bl3, out);
}

// round 17
// speedup vs baseline: 1.0854x; 1.0854x over previous
#include <cuda_runtime.h>
#include <cuda_bf16.h>
#include <cstdint>

#define NN 20000
#define NE 640000
#define P_PATH 512
#define S_SUB 64
#define DHID 256
#define SCAN_B 79  // ceil(20000/256)

typedef unsigned long long ull;

// ---------------- scratch (static device globals; no allocation) ----------------
static __device__ __align__(16) float g_agg[NN * 128];
static __device__ __align__(16) float g_part[NN * 256];
static __device__ __align__(16) float g_h1[NN * 24];
static __device__ __align__(16) float g_h2[NN * 64];
static __device__ __align__(16) float g_h3[NN * 128];
static __device__ __align__(16) float g_h4[NN * 256];
static __device__ __align__(16) float g_w3t[64 * 128];     // W3^T [K=64][N=128]
static __device__ __align__(16) float g_w4t[128 * 256];    // W4^T [K=128][N=256]
static __device__ __align__(16) float g_wiT[3 * 256 * 1024];  // Wih[:,256:512]^T [k][d][j]
static __device__ int g_deg[NN];
static __device__ int g_off[NN + 1];
static __device__ int g_cur[NN];
static __device__ int g_bsum[SCAN_B];
static __device__ int g_bpre[SCAN_B];
static __device__ int g_ticket;
static __device__ int g_ticket2;
static __device__ int g_srcs[NE];
static __device__ float g_c[3 * 1024];
static __device__ __align__(16) float g_r0[3 * P_PATH * 256];
static __device__ __align__(16) float g_gates[3 * P_PATH * 1024];
static __device__ float g_xg[P_PATH];

__device__ __forceinline__ float sigm(float x) { return 1.f / (1.f + __expf(-x)); }

__device__ __forceinline__ void ffma2(ull& acc, ull a, ull b) {
    asm("fma.rn.f32x2 %0, %1, %2, %0;" : "+l"(acc) : "l"(a), "l"(b));
}
__device__ __forceinline__ float hsum2(ull v) {
    return __uint_as_float((unsigned)v) + __uint_as_float((unsigned)(v >> 32));
}

// ---------------- CSR build ----------------
__global__ void hist_kernel(const int* __restrict__ dst, int* __restrict__ deg, int E) {
    int e = blockIdx.x * blockDim.x + threadIdx.x;
    if (e < E) atomicAdd(&deg[dst[e]], 1);
}

__global__ void blocksum_scan(const int* __restrict__ deg, int* __restrict__ bsum,
                              int* __restrict__ bpre, int* __restrict__ off,
                              int* __restrict__ ticket) {
    __shared__ int sred[8];
    int i = blockIdx.x * 256 + threadIdx.x;
    int v = (i < NN) ? deg[i] : 0;
    for (int o = 16; o; o >>= 1) v += __shfl_down_sync(0xffffffffu, v, o);
    if ((threadIdx.x & 31) == 0) sred[threadIdx.x >> 5] = v;
    __syncthreads();
    if (threadIdx.x == 0) {
        int t = 0;
#pragma unroll
        for (int j = 0; j < 8; j++) t += sred[j];
        bsum[blockIdx.x] = t;
        __threadfence();
        int tk = atomicAdd(ticket, 1);
        if (tk == SCAN_B - 1) {
            int acc = 0;
            for (int b = 0; b < SCAN_B; b++) {
                bpre[b] = acc;
                acc += bsum[b];
            }
            off[NN] = acc;
            *ticket = 0;  // reset for next graph replay
        }
    }
}

__global__ void write_off(const int* __restrict__ deg, const int* __restrict__ bpre,
                          int* __restrict__ off, int* __restrict__ cur) {
    __shared__ int sd[256];
    int t = threadIdx.x;
    int i = blockIdx.x * 256 + t;
    int dv = (i < NN) ? deg[i] : 0;
    sd[t] = dv;
    __syncthreads();
    for (int o = 1; o < 256; o <<= 1) {
        int v = (t >= o) ? sd[t - o] : 0;
        __syncthreads();
        sd[t] += v;
        __syncthreads();
    }
    if (i < NN) {
        int excl = bpre[blockIdx.x] + sd[t] - dv;
        off[i] = excl;
        cur[i] = excl;
    }
}

__global__ void bucket_kernel(const int* __restrict__ src, const int* __restrict__ dst,
                              int* __restrict__ cur, int* __restrict__ srcs, int E) {
    int e = blockIdx.x * blockDim.x + threadIdx.x;
    if (e < E) {
        int p = atomicAdd(&cur[dst[e]], 1);
        srcs[p] = src[e];
    }
}

// ---------------- merged W transposes + wiT + xg zero ----------------
__global__ void wtrans_all(const float* __restrict__ W3, float* __restrict__ w3t,
                           const float* __restrict__ W4, float* __restrict__ w4t,
                           const float* __restrict__ Wih, float* __restrict__ wiT,
                           float* __restrict__ xg) {
    int i = blockIdx.x * 256 + threadIdx.x;
    if (i < P_PATH) xg[i] = 0.f;
    if (i < 64 * 128) {
        int n = i % 128, k = i / 128;
        w3t[k * 128 + n] = W3[n * 64 + k];
    } else if (i < 64 * 128 + 128 * 256) {
        int j = i - 64 * 128;
        int n = j % 256, k = j / 256;
        w4t[k * 256 + n] = W4[n * 128 + k];
    }
    int i2 = i - (64 * 128 + 128 * 256);
    if (i2 >= 0 && i2 < 3 * 256 * 1024) {
        // wiT[(k*256 + d)*1024 + j] = Wih[(k*1024 + j)*512 + 256 + d]
        int j = i2 % 1024;
        int rem = i2 / 1024;
        int d = rem % 256;
        int k = rem / 256;
        wiT[i2] = Wih[((size_t)(k * 1024 + j)) * 512 + 256 + d];
    }
}

// ---------------- direct gather aggregation (large D) ----------------
template <int D>
__global__ void aggregate_k(const float* __restrict__ h, const int* __restrict__ off,
                            const int* __restrict__ srcs, float* __restrict__ outp) {
    constexpr int C = D / 4;
    int idx = blockIdx.x * blockDim.x + threadIdx.x;
    if (idx >= NN * C) return;
    int node = idx / C;
    int c = idx - node * C;
    const float4* hp = reinterpret_cast<const float4*>(h);
    float4 acc = hp[(size_t)node * C + c];
    int s0 = off[node], s1 = off[node + 1];
#pragma unroll 8
    for (int j = s0; j < s1; j++) {
        int s = __ldg(&srcs[j]);
        float4 v = hp[(size_t)s * C + c];
        acc.x += v.x;
        acc.y += v.y;
        acc.z += v.z;
        acc.w += v.w;
    }
    reinterpret_cast<float4*>(outp)[idx] = acc;
}

// ---------------- sliced aggregation (small D) ----------------
template <int D, int NS>
__global__ void aggregate_sliced(const float* __restrict__ h, const int* __restrict__ off,
                                 const int* __restrict__ srcs, float* __restrict__ part) {
    constexpr int C = D / 4;
    int idx = blockIdx.x * blockDim.x + threadIdx.x;
    if (idx >= NN * C * NS) return;
    int slice = idx / (NN * C);
    int rem = idx - slice * NN * C;
    int node = rem / C;
    int c = rem - node * C;
    const float4* hp = reinterpret_cast<const float4*>(h);
    int s0 = off[node], s1 = off[node + 1];
    int len = s1 - s0;
    int a = s0 + (len * slice) / NS;
    int b = s0 + (len * (slice + 1)) / NS;
    float4 acc = {0.f, 0.f, 0.f, 0.f};
#pragma unroll 4
    for (int j = a; j < b; j++) {
        int s = __ldg(&srcs[j]);
        float4 v = hp[(size_t)s * C + c];
        acc.x += v.x;
        acc.y += v.y;
        acc.z += v.z;
        acc.w += v.w;
    }
    reinterpret_cast<float4*>(part)[idx] = acc;
}

// ---------------- small GIN GEMM (layers 1-2): out = relu((xin + sum part) @ W^T + b) ------
template <int K, int N, int NP, int T, int RPB, int NSLICE>
__global__ void gemm_relu(const float* __restrict__ xin, const float* __restrict__ part,
                          const float* __restrict__ W, const float* __restrict__ b,
                          float* __restrict__ out, int nrows) {
    constexpr int LDK = K + 4;
    constexpr int G = T / NP;
    constexpr int RPT = RPB / G;
    extern __shared__ float sm[];
    float* sW = sm;
    float* sR = sm + N * LDK;
    int tid = threadIdx.x;
    for (int i = tid; i < K * N; i += T) {
        int j = i / K, k = i - j * K;
        sW[j * LDK + k] = W[i];
    }
    int row0 = blockIdx.x * RPB;
    for (int i = tid; i < RPB * K; i += T) {
        int r = i / K, k = i - r * K;
        int row = row0 + r;
        float v = 0.f;
        if (row < nrows) {
            v = xin[(size_t)row * K + k];
#pragma unroll
            for (int s = 0; s < NSLICE; s++) v += part[((size_t)s * NN + row) * K + k];
        }
        sR[i] = v;
    }
    __syncthreads();
    int j = tid % NP;
    int rg = tid / NP;
    if (j < N) {
        float acc[RPT];
#pragma unroll
        for (int t = 0; t < RPT; t++) acc[t] = 0.f;
        for (int k = 0; k < K; k += 4) {
            float4 w4 = *reinterpret_cast<const float4*>(&sW[j * LDK + k]);
#pragma unroll
            for (int t = 0; t < RPT; t++) {
                float4 s4 = *reinterpret_cast<const float4*>(&sR[(rg + t * G) * K + k]);
                acc[t] += s4.x * w4.x + s4.y * w4.y + s4.z * w4.z + s4.w * w4.w;
            }
        }
        float bj = b[j];
#pragma unroll
        for (int t = 0; t < RPT; t++) {
            int row = row0 + rg + t * G;
            if (row < nrows) out[(size_t)row * N + j] = fmaxf(acc[t] + bj, 0.f);
        }
    }
}

// ---------------- register-tiled GEMM (layers 3-4), k-paired f32x2 ----------------
template <int K, int N>
__global__ void gemm_rt(const float* __restrict__ X, const float* __restrict__ WT,
                        const float* __restrict__ b, float* __restrict__ out, int nrows) {
    constexpr int TM = 64, TN = 64;
    constexpr int RSF = K + 2;
    extern __shared__ float sm[];
    float* sA = sm;            // [TM][K]
    float* sBt = sm + TM * K;  // [TN][RSF]
    int tid = threadIdx.x;
    int row0 = blockIdx.x * TM, n0 = blockIdx.y * TN;

    float4* sA4 = reinterpret_cast<float4*>(sA);
    for (int i = tid; i < TM * (K / 4); i += 256) {
        int kq = i % (K / 4), m = i / (K / 4);
        int row = row0 + m;
        float4 v = {0.f, 0.f, 0.f, 0.f};
        if (row < nrows) v = *reinterpret_cast<const float4*>(&X[(size_t)row * K + 4 * kq]);
        sA4[m * (K / 4) + kq] = v;
    }
    for (int i = tid; i < K * (TN / 4); i += 256) {
        int nq = i % (TN / 4), k = i / (TN / 4);
        float4 v = *reinterpret_cast<const float4*>(&WT[(size_t)k * N + n0 + 4 * nq]);
        sBt[(4 * nq + 0) * RSF + k] = v.x;
        sBt[(4 * nq + 1) * RSF + k] = v.y;
        sBt[(4 * nq + 2) * RSF + k] = v.z;
        sBt[(4 * nq + 3) * RSF + k] = v.w;
    }
    __syncthreads();

    int tx = tid % 16, ty = tid / 16;
    ull c2[4][4];
#pragma unroll
    for (int i = 0; i < 4; i++)
#pragma unroll
        for (int j = 0; j < 4; j++) c2[i][j] = 0ull;

#pragma unroll 8
    for (int kp = 0; kp < K / 2; kp++) {
        ull av[4], bv[4];
#pragma unroll
        for (int i = 0; i < 4; i++)
            av[i] = *reinterpret_cast<const ull*>(&sA[(ty * 4 + i) * K + 2 * kp]);
#pragma unroll
        for (int jj = 0; jj < 4; jj++)
            bv[jj] = *reinterpret_cast<const ull*>(&sBt[(tx + 16 * jj) * RSF + 2 * kp]);
#pragma unroll
        for (int i = 0; i < 4; i++)
#pragma unroll
            for (int jj = 0; jj < 4; jj++) ffma2(c2[i][jj], av[i], bv[jj]);
    }

#pragma unroll
    for (int i = 0; i < 4; i++) {
        int row = row0 + ty * 4 + i;
        if (row < nrows) {
#pragma unroll
            for (int jj = 0; jj < 4; jj++) {
                int n = n0 + tx + 16 * jj;
                out[(size_t)row * N + n] = fmaxf(hsum2(c2[i][jj]) + b[n], 0.f);
            }
        }
    }
}

// ---------------- gates_rt: gates = r0 @ wiT + cvec  (coalesced register-tiled) ----------
// r0: [3][P][256], wiT: [3][256][1024], gates: [3][P][1024]. Grid (P/64, 1024/64, 3).
__global__ void gates_rt(const float* __restrict__ r0, const float* __restrict__ wiT,
                         const float* __restrict__ c, float* __restrict__ gates) {
    constexpr int TM = 64, TN = 64, KC = 128;
    constexpr int RSF = KC + 2;  // 130
    extern __shared__ float sm[];
    float* sA = sm;             // [TM][KC]
    float* sBt = sm + TM * KC;  // [TN][RSF]
    int tid = threadIdx.x;
    int row0 = blockIdx.x * TM, n0 = blockIdx.y * TN, k = blockIdx.z;
    int tx = tid % 16, ty = tid / 16;

    ull c2[4][4];
#pragma unroll
    for (int i = 0; i < 4; i++)
#pragma unroll
        for (int j = 0; j < 4; j++) c2[i][j] = 0ull;

    for (int kc = 0; kc < 2; kc++) {
        float4* sA4 = reinterpret_cast<float4*>(sA);
        const float* abase = r0 + ((size_t)(k * P_PATH) + row0) * 256 + kc * KC;
        for (int i = tid; i < TM * (KC / 4); i += 256) {
            int kq = i % (KC / 4), m = i / (KC / 4);
            sA4[m * (KC / 4) + kq] =
                *reinterpret_cast<const float4*>(&abase[(size_t)m * 256 + 4 * kq]);
        }
        const float* bbase = wiT + ((size_t)(k * 256 + kc * KC)) * 1024 + n0;
        for (int i = tid; i < KC * (TN / 4); i += 256) {
            int nq = i % (TN / 4), kk = i / (TN / 4);
            float4 v = *reinterpret_cast<const float4*>(&bbase[(size_t)kk * 1024 + 4 * nq]);
            sBt[(4 * nq + 0) * RSF + kk] = v.x;
            sBt[(4 * nq + 1) * RSF + kk] = v.y;
            sBt[(4 * nq + 2) * RSF + kk] = v.z;
            sBt[(4 * nq + 3) * RSF + kk] = v.w;
        }
        __syncthreads();
#pragma unroll 8
        for (int kp = 0; kp < KC / 2; kp++) {
            ull av[4], bv[4];
#pragma unroll
            for (int i = 0; i < 4; i++)
                av[i] = *reinterpret_cast<const ull*>(&sA[(ty * 4 + i) * KC + 2 * kp]);
#pragma unroll
            for (int jj = 0; jj < 4; jj++)
                bv[jj] = *reinterpret_cast<const ull*>(&sBt[(tx + 16 * jj) * RSF + 2 * kp]);
#pragma unroll
            for (int i = 0; i < 4; i++)
#pragma unroll
                for (int jj = 0; jj < 4; jj++) ffma2(c2[i][jj], av[i], bv[jj]);
        }
        __syncthreads();
    }

#pragma unroll
    for (int i = 0; i < 4; i++) {
        int row = row0 + ty * 4 + i;
#pragma unroll
        for (int jj = 0; jj < 4; jj++) {
            int n = n0 + tx + 16 * jj;
            gates[((size_t)(k * P_PATH) + row) * 1024 + n] = hsum2(c2[i][jj]) + c[k * 1024 + n];
        }
    }
}

// ---------------- attention (R9 form: grid (P+4, 3); fused cvec/LSTM/xg/final) -------------
template <int PASS>
__global__ void attn_kernel(const float* __restrict__ h4, const int* __restrict__ pn,
                            const float* __restrict__ gates, const float* __restrict__ bih,
                            const float* __restrict__ bhh, const float* __restrict__ Wg,
                            const float* __restrict__ Wih, const float* __restrict__ Whh,
                            float* __restrict__ cvec, float* __restrict__ r0out,
                            float* __restrict__ xg, int* __restrict__ ticket2,
                            const float* __restrict__ bg, const float* __restrict__ Wl1,
                            const float* __restrict__ bl1, const float* __restrict__ Wl2,
                            const float* __restrict__ bl2, const float* __restrict__ Wl3,
                            const float* __restrict__ bl3, float* __restrict__ out) {
    int p = blockIdx.x, k = blockIdx.y;
    extern __shared__ float smdyn[];
    float* sx = smdyn;
    float* sq = smdyn + 64 * 256;
    float* dots = sq + 256;
    int* spn = (int*)(dots + 64);
    int tid = threadIdx.x;

    if (PASS == 0 && p >= P_PATH) {  // cvec worker blocks
        int j = (p - P_PATH) * 256 + tid;
        {
            const float* bi = bih + k * 1024;
            const float* bh = bhh + k * 1024;
            float gi = bi[tid] + bh[tid];
            float gg = bi[512 + tid] + bh[512 + tid];
            float go = bi[768 + tid] + bh[768 + tid];
            float cs = sigm(gi) * tanhf(gg);
            sq[tid] = sigm(go) * tanhf(cs);
        }
        __syncthreads();
        const float* wi = Wih + ((size_t)k * 1024 + j) * 512;
        const float* wh = Whh + ((size_t)k * 1024 + j) * 256;
        float acc = bih[k * 1024 + j] + bhh[k * 1024 + j];
        for (int d = 0; d < 256; d += 4) {
            float4 a = *reinterpret_cast<const float4*>(wi + d);
            float4 bq = *reinterpret_cast<const float4*>(wh + d);
            float4 s = *reinterpret_cast<const float4*>(&sq[d]);
            acc += (a.x + bq.x) * s.x + (a.y + bq.y) * s.y + (a.z + bq.z) * s.z +
                   (a.w + bq.w) * s.w;
        }
        cvec[k * 1024 + j] = acc;
        return;
    }

    {
        const float* bi = bih + k * 1024;
        const float* bh = bhh + k * 1024;
        float bgi = bi[tid] + bh[tid];
        float bgg = bi[512 + tid] + bh[512 + tid];
        float bgo = bi[768 + tid] + bh[768 + tid];
        float cs0 = sigm(bgi) * tanhf(bgg);
        if (PASS == 0) {
            sq[tid] = sigm(bgo) * tanhf(cs0);
        } else {
            const float* g = gates + ((size_t)(k * P_PATH + p)) * 1024;
            float gi = g[tid], gf = g[256 + tid], gg = g[512 + tid], go = g[768 + tid];
            float cs = sigm(gf) * cs0 + sigm(gi) * tanhf(gg);
            sq[tid] = sigm(go) * tanhf(cs);
        }
    }
    if (tid < 64) spn[tid] = pn[p * 64 + tid];
    __syncthreads();

    const float4* h4v = reinterpret_cast<const float4*>(h4);
    float4* sxv = reinterpret_cast<float4*>(sx);
    for (int i = tid; i < 64 * 64; i += 256) {
        int s = i >> 6, c = i & 63;
        sxv[i] = h4v[(size_t)spn[s] * 64 + c];
    }
    __syncthreads();

    int w = tid >> 5, lane = tid & 31;
    for (int s = w; s < 64; s += 8) {
        const float* xr = sx + s * 256;
        float part = 0.f;
#pragma unroll
        for (int m = 0; m < 8; m++) part += xr[lane + 32 * m] * sq[lane + 32 * m];
        for (int off = 16; off; off >>= 1) part += __shfl_down_sync(0xffffffffu, part, off);
        if (lane == 0) dots[s] = part;
    }
    __syncthreads();
    if (w == 0) {
        float a = dots[lane], b = dots[lane + 32];
        float mx = fmaxf(a, b);
        for (int off = 16; off; off >>= 1) mx = fmaxf(mx, __shfl_xor_sync(0xffffffffu, mx, off));
        float e0 = __expf(a - mx), e1 = __expf(b - mx);
        float sum = e0 + e1;
        for (int off = 16; off; off >>= 1) sum += __shfl_xor_sync(0xffffffffu, sum, off);
        float inv = 1.f / sum;
        dots[lane] = e0 * inv;
        dots[lane + 32] = e1 * inv;
    }
    __syncthreads();
    float acc = 0.f;
#pragma unroll 8
    for (int s = 0; s < 64; s++) acc += dots[s] * sx[s * 256 + tid];

    if (PASS == 0) {
        r0out[((size_t)k * P_PATH + p) * 256 + tid] = acc;
        return;
    }

    float part = sq[tid] * Wg[k * 512 + tid] + acc * Wg[k * 512 + 256 + tid];
    __syncthreads();
    for (int off = 16; off; off >>= 1) part += __shfl_xor_sync(0xffffffffu, part, off);
    if (lane == 0) dots[w] = part;
    __syncthreads();
    __shared__ int s_last;
    if (tid == 0) {
        float t = 0.f;
#pragma unroll
        for (int i = 0; i < 8; i++) t += dots[i];
        atomicAdd(&xg[p], t);
        __threadfence();
        int tk = atomicAdd(ticket2, 1);
        s_last = (tk == 3 * P_PATH - 1);
    }
    __syncthreads();
    if (!s_last) return;

    // ---- final MLP (last-arriving block) ----
    __threadfence();
    float* sxg = sx;
    float* sz1 = sx + 512;
    float* sz2 = sx + 512 + 256;
    float bgv = bg[0];
    sxg[tid] = xg[tid] + bgv;
    sxg[tid + 256] = xg[tid + 256] + bgv;
    __syncthreads();
    {
        float a = bl1[tid];
        const float* wv = Wl1 + (size_t)tid * 512;
        for (int q = 0; q < 512; q += 4) {
            float4 w4 = *reinterpret_cast<const float4*>(wv + q);
            float4 x4 = *reinterpret_cast<const float4*>(&sxg[q]);
            a += w4.x * x4.x + w4.y * x4.y + w4.z * x4.z + w4.w * x4.w;
        }
        sz1[tid] = tanhf(a);
    }
    __syncthreads();
    if (tid < 64) {
        float bacc = bl2[tid];
        const float* w2 = Wl2 + (size_t)tid * 256;
        for (int hh = 0; hh < 256; hh += 4) {
            float4 w4 = *reinterpret_cast<const float4*>(w2 + hh);
            float4 z4 = *reinterpret_cast<const float4*>(&sz1[hh]);
            bacc += w4.x * z4.x + w4.y * z4.y + w4.z * z4.z + w4.w * z4.w;
        }
        sz2[tid] = fmaxf(bacc, 0.f);
    }
    __syncthreads();
    if (tid == 0) {
        float cacc = bl3[0];
        for (int j = 0; j < 64; j++) cacc += sz2[j] * Wl3[j];
        out[0] = 1.f / (1.f + __expf(-cacc));
        *ticket2 = 0;  // reset for next graph replay
    }
}

// ---------------- host launcher ----------------
extern "C" void kernel_launch(void* const* d_in, const int* in_sizes, int n_in,
                              void* d_out, int out_size) {
    const float* h = (const float*)d_in[0];
    const int* src = (const int*)d_in[1];
    const int* dst = (const int*)d_in[2];
    const int* pn = (const int*)d_in[3];
    const float* W1 = (const float*)d_in[4];
    const float* b1 = (const float*)d_in[5];
    const float* W2 = (const float*)d_in[6];
    const float* b2 = (const float*)d_in[7];
    const float* W3 = (const float*)d_in[8];
    const float* b3 = (const float*)d_in[9];
    const float* W4 = (const float*)d_in[10];
    const float* b4 = (const float*)d_in[11];
    const float* Wih = (const float*)d_in[12];
    const float* Whh = (const float*)d_in[13];
    const float* bih = (const float*)d_in[14];
    const float* bhh = (const float*)d_in[15];
    const float* Wg = (const float*)d_in[16];
    const float* bg = (const float*)d_in[17];
    const float* Wl1 = (const float*)d_in[18];
    const float* bl1 = (const float*)d_in[19];
    const float* Wl2 = (const float*)d_in[20];
    const float* bl2 = (const float*)d_in[21];
    const float* Wl3 = (const float*)d_in[22];
    const float* bl3 = (const float*)d_in[23];
    int E = in_sizes[1];
    float* out = (float*)d_out;

    float *agg, *part, *h1, *h2, *h3, *h4, *w3t, *w4t, *wiT, *cvec, *r0, *gates, *xg;
    int *deg, *off, *cur, *srcs, *bsum, *bpre, *ticket, *ticket2;
    cudaGetSymbolAddress((void**)&agg, g_agg);
    cudaGetSymbolAddress((void**)&part, g_part);
    cudaGetSymbolAddress((void**)&h1, g_h1);
    cudaGetSymbolAddress((void**)&h2, g_h2);
    cudaGetSymbolAddress((void**)&h3, g_h3);
    cudaGetSymbolAddress((void**)&h4, g_h4);
    cudaGetSymbolAddress((void**)&w3t, g_w3t);
    cudaGetSymbolAddress((void**)&w4t, g_w4t);
    cudaGetSymbolAddress((void**)&wiT, g_wiT);
    cudaGetSymbolAddress((void**)&cvec, g_c);
    cudaGetSymbolAddress((void**)&r0, g_r0);
    cudaGetSymbolAddress((void**)&gates, g_gates);
    cudaGetSymbolAddress((void**)&xg, g_xg);
    cudaGetSymbolAddress((void**)&deg, g_deg);
    cudaGetSymbolAddress((void**)&off, g_off);
    cudaGetSymbolAddress((void**)&cur, g_cur);
    cudaGetSymbolAddress((void**)&srcs, g_srcs);
    cudaGetSymbolAddress((void**)&bsum, g_bsum);
    cudaGetSymbolAddress((void**)&bpre, g_bpre);
    cudaGetSymbolAddress((void**)&ticket, g_ticket);
    cudaGetSymbolAddress((void**)&ticket2, g_ticket2);

    const int smem1 = (24 * 12 + 32 * 8) * 4;
    const int smem2 = (64 * 28 + 32 * 24) * 4;
    const int rt3_smem = (64 * 64 + 64 * 66) * 4;    // ~33.3 KB
    const int rt4_smem = (64 * 128 + 64 * 130) * 4;  // ~66.0 KB
    const int gates_smem = (64 * 128 + 64 * 130) * 4;  // ~66.0 KB
    cudaFuncSetAttribute(gemm_rt<64, 128>, cudaFuncAttributeMaxDynamicSharedMemorySize,
                         rt3_smem);
    cudaFuncSetAttribute(gemm_rt<128, 256>, cudaFuncAttributeMaxDynamicSharedMemorySize,
                         rt4_smem);
    cudaFuncSetAttribute(gates_rt, cudaFuncAttributeMaxDynamicSharedMemorySize, gates_smem);
    const int attn_smem = (64 * 256 + 256 + 64 + 64) * 4;
    cudaFuncSetAttribute(attn_kernel<0>, cudaFuncAttributeMaxDynamicSharedMemorySize, attn_smem);
    cudaFuncSetAttribute(attn_kernel<1>, cudaFuncAttributeMaxDynamicSharedMemorySize, attn_smem);

    // ---- prologue + CSR build ----
    cudaMemsetAsync(deg, 0, NN * sizeof(int));
    const int wtrans_items = 64 * 128 + 128 * 256 + 3 * 256 * 1024;
    wtrans_all<<<(wtrans_items + 255) / 256, 256>>>(W3, w3t, W4, w4t, Wih, wiT, xg);
    hist_kernel<<<(E + 255) / 256, 256>>>(dst, deg, E);
    blocksum_scan<<<SCAN_B, 256>>>(deg, bsum, bpre, off, ticket);
    write_off<<<SCAN_B, 256>>>(deg, bpre, off, cur);
    bucket_kernel<<<(E + 255) / 256, 256>>>(src, dst, cur, srcs, E);

    // ---- 4 GIN layers ----
    aggregate_sliced<8, 8><<<(NN * 2 * 8 + 255) / 256, 256>>>(h, off, srcs, part);
    gemm_relu<8, 24, 32, 256, 32, 8><<<(NN + 31) / 32, 256, smem1>>>(h, part, W1, b1, h1, NN);

    aggregate_sliced<24, 4><<<(NN * 6 * 4 + 255) / 256, 256>>>(h1, off, srcs, part);
    gemm_relu<24, 64, 64, 256, 32, 4><<<(NN + 31) / 32, 256, smem2>>>(h1, part, W2, b2, h2, NN);

    aggregate_k<64><<<(NN * 16 + 255) / 256, 256>>>(h2, off, srcs, agg);
    gemm_rt<64, 128><<<dim3((NN + 63) / 64, 2), 256, rt3_smem>>>(agg, w3t, b3, h3, NN);

    aggregate_k<128><<<(NN * 32 + 255) / 256, 256>>>(h3, off, srcs, agg);
    gemm_rt<128, 256><<<dim3((NN + 63) / 64, 4), 256, rt4_smem>>>(agg, w4t, b4, h4, NN);

    // ---- Set2Set (R9 form; gates via coalesced register-tiled GEMM) ----
    attn_kernel<0><<<dim3(P_PATH + 4, 3), 256, attn_smem>>>(
        h4, pn, nullptr, bih, bhh, Wg, Wih, Whh, cvec, r0, xg, ticket2, bg, Wl1, bl1, Wl2, bl2,
        Wl3, bl3, out);
    gates_rt<<<dim3(P_PATH / 64, 1024 / 64, 3), 256, gates_smem>>>(r0, wiT, cvec, gates);
    attn_kernel<1><<<dim3(P_PATH, 3), 256, attn_smem>>>(
        h4, pn, gates, bih, bhh, Wg, Wih, Whh, cvec, r0, xg, ticket2, bg, Wl1, bl1, Wl2, bl2,
        Wl3, bl3, out);
}